// round 9
// baseline (speedup 1.0000x reference)
#include <cuda_runtime.h>
#include <cstdint>

// Compact per-row maps (no clearing needed):
//   g_tok[d*T + rank] = global token id of the rank-th kept token in row d
//   g_total/g_zero: kept count, special zeroed slot (-1 if none)
#define MAX_D  64
#define MAX_DT (8 * 32768)
__device__ int g_tok[MAX_DT];
__device__ int g_total[MAX_D];
__device__ int g_zero[MAX_D];
__device__ volatile int g_ready[MAX_D];   // 0 at process start; reset each launch
__device__ unsigned g_done;               // finished-block counter, reset each launch

__device__ __forceinline__ int mask_at(const void* mask, int mtype, long i) {
    if (mtype == 1) return ((const int*)mask)[i] != 0;          // int32
    if (mtype == 2) return ((const float*)mask)[i] != 0.0f;     // float32
    return ((const uint8_t*)mask)[i] != 0;                      // uint8/bool
}

// Setup for row d: mask scan -> g_tok/g_total/g_zero + tail outputs, then set
// g_ready[d]. Runs in 8 of ~32k blocks; __noinline__ + launch_bounds cap means
// its register demand spills to local instead of taxing the copy blocks.
__device__ __noinline__ void setup_row(const void* __restrict__ mask,
                                       const int* __restrict__ n_valid,
                                       const int* __restrict__ index,
                                       float* __restrict__ out_tail,
                                       int D, int T, int M, int d)
{
    const int t  = threadIdx.x;
    const int NT = blockDim.x;

    // mask dtype probe over this row's first T bytes:
    // float32: 1.0f bytes 00 00 80 3f -> some byte > 1
    // int32  : nonzero bytes only at pos%4==0
    // uint8  : nonzero at pos%4!=0 (w.h.p.)
    __shared__ int s_gt1, s_nzmod;
    if (t == 0) { s_gt1 = 0; s_nzmod = 0; }
    __syncthreads();
    {
        const uint8_t* mb = (const uint8_t*)mask + (long)d * T;
        int gt1 = 0, nzmod = 0;
        for (int i = t; i < T; i += NT) {
            uint8_t b = mb[i];
            if (b > 1) gt1 = 1;
            else if (b != 0 && (i & 3)) nzmod = 1;
        }
        if (gt1)   atomicOr(&s_gt1, 1);
        if (nzmod) atomicOr(&s_nzmod, 1);
    }
    __syncthreads();

    const int mtype = s_gt1 ? 2 : (s_nzmod ? 0 : 1);
    const long mbase = (long)d * T;

    const int chunk = (T + NT - 1) / NT;
    const int start = t * chunk;

    int cnt = 0;
    for (int j = 0; j < chunk; ++j) {
        int tt = start + j;
        if (tt < T && mask_at(mask, mtype, mbase + tt)) cnt++;
    }

    // Block exclusive scan over per-thread counts.
    const unsigned lane = t & 31u;
    const unsigned wid  = t >> 5;
    int v = cnt;
    #pragma unroll
    for (int off = 1; off < 32; off <<= 1) {
        int n = __shfl_up_sync(0xffffffffu, v, off);
        if (lane >= (unsigned)off) v += n;
    }
    __shared__ int warp_tot[32];
    __shared__ int warp_pref[33];
    if (lane == 31) warp_tot[wid] = v;
    __syncthreads();
    if (t == 0) {
        int s = 0;
        int nw = (NT + 31) >> 5;
        for (int w = 0; w < nw; ++w) { warp_pref[w] = s; s += warp_tot[w]; }
        warp_pref[nw] = s;
    }
    __syncthreads();
    const int excl  = warp_pref[wid] + (v - cnt);
    const int total = warp_pref[(NT + 31) >> 5];

    int rank = excl;
    int* tok = g_tok + (long)d * T;
    for (int j = 0; j < chunk; ++j) {
        int tt = start + j;
        if (tt < T && mask_at(mask, mtype, mbase + tt)) {
            tok[rank++] = d * T + tt;      // global token id, in rank order
        }
    }

    if (t == 0) {
        const int idx0 = index[d];
        g_total[d] = total;
        // First token masked -> offsets[0] = -1 -> slot (index-1) mod M is
        // set(0)+add(0). Never collides with kept slots (total < M).
        int zs = -1;
        if (T > 0 && !mask_at(mask, mtype, mbase) && total < M) {
            zs = idx0 - 1;
            if (zs < 0) zs += M;
        }
        g_zero[d] = zs;
        if (out_tail) {
            long nv = (long)n_valid[d] + total;
            if (nv > M) nv = M;
            out_tail[d]     = (float)nv;                     // new_n_valid
            out_tail[D + d] = (float)((idx0 + total) % M);   // new_index
        }
    }

    __syncthreads();
    __threadfence();                 // publish g_* before the flag
    if (t == 0) g_ready[d] = 1;
}

// Slow write path (ranks that may come from acts / the zeroed slot). Runs in
// ~1.5% of blocks, scheduled long after the row's setup block; __noinline__
// keeps its register cost out of the fast path.
__device__ __noinline__ void write_slow(const float4* __restrict__ cache,
                                        const float4* __restrict__ acts,
                                        float4* __restrict__ out,
                                        int d, int idx0, int rk, int n,
                                        int T, int M, long rowd)
{
    const int t  = threadIdx.x;
    const int NT = blockDim.x;

    if (t == 0) { while (g_ready[d] == 0) __nanosleep(64); }
    __syncthreads();
    __threadfence();                // order g_* reads after flag

    const int total = g_total[d];
    const int zslot = g_zero[d];
    const int* tok  = g_tok + (long)d * T;

    for (int i = 0; i < n; ++i) {
        int rank = rk + i; if (rank >= M) rank -= M;
        int s = idx0 + rank; if (s >= M) s -= M;
        const long r = rowd + s;
        const bool fa = rank < total;
        const int  tk = fa ? tok[rank] : 0;
        const float4* p = (fa ? acts + (long)tk * NT : cache + r * NT) + t;
        float4 v = __ldcs(p);
        if (s == zslot) v = make_float4(0.f, 0.f, 0.f, 0.f);
        __stcs(out + r * NT + t, v);
    }
}

// Single fused kernel. Grid (nb_per_d + 1, D), blockDim = DIM/4.
//  blockIdx.x == 0  : setup for row d.
//  blockIdx.x == x+1: covers ring ranks T+8x .. T+8x+7 (mod M) of row d.
//    ranks in [T, M-2]  -> pure cache->out copy, no dependency on setup.
//    ranks wrapping / M-1 -> slow path with flag wait (scheduled ~3.5k blocks
//    after the row's setup block, so the wait never engages in practice).
__global__ void __launch_bounds__(192, 8)
fused_kernel(const float4* __restrict__ cache,
             const float4* __restrict__ acts,
             const void*  __restrict__ mask,
             const int*   __restrict__ n_valid,
             const int*   __restrict__ index,
             float4* __restrict__ out,
             float*  __restrict__ out_tail,
             int D, int T, int M)
{
    const int t  = threadIdx.x;
    const int NT = blockDim.x;       // = DIM/4 = 192
    const int d  = blockIdx.y;

    if (blockIdx.x == 0) {
        setup_row(mask, n_valid, index, out_tail, D, T, M, d);
    } else {
        const int x    = blockIdx.x - 1;
        const int k0   = x * 8;                 // rank = T + k0 + i
        const int idx0 = index[d];              // raw input: no setup dependency
        const long rowd = (long)d * M;
        const int rk   = T + k0;

        if (k0 + 7 < M && rk + 7 < M - 1) {
            // ranks in [T, M-2]: pure cache -> out, slots = (idx0+rank)%M
            long r[8];
            #pragma unroll
            for (int i = 0; i < 8; ++i) {
                int s = idx0 + rk + i;          // < 2M-2: one subtract suffices
                if (s >= M) s -= M;
                r[i] = rowd + s;
            }
            float4 v[8];
            #pragma unroll
            for (int i = 0; i < 8; ++i) v[i] = __ldcs(cache + r[i] * NT + t);
            #pragma unroll
            for (int i = 0; i < 8; ++i) __stcs(out + r[i] * NT + t, v[i]);
        } else {
            const int n = (k0 + 8 <= M) ? 8 : (M - k0);
            write_slow(cache, acts, out, d, idx0, rk, n, T, M, rowd);
        }
    }

    // -------- launch-epilogue: last finished block resets the flags --------
    if (t == 0) {
        const unsigned nb = gridDim.x * gridDim.y;
        const unsigned v = atomicAdd(&g_done, 1u);
        if (v == nb - 1u) {
            for (int i = 0; i < D && i < MAX_D; ++i) g_ready[i] = 0;
            __threadfence();
            g_done = 0;
        }
    }
}

extern "C" void kernel_launch(void* const* d_in, const int* in_sizes, int n_in,
                              void* d_out, int out_size)
{
    const float* cache   = (const float*)d_in[0];
    const float* acts    = (const float*)d_in[1];
    const void*  mask    = (const void*)d_in[2];
    const int*   n_valid = (const int*)d_in[3];
    const int*   index   = (const int*)d_in[4];

    const int  D      = in_sizes[3];                      // 8
    const long DT     = (long)in_sizes[2];                // D*T
    const int  T      = (int)(DT / D);                    // 4096
    const int  DIM    = (int)((long)in_sizes[1] / DT);    // 768
    const long cacheN = (long)in_sizes[0];                // D*M*DIM
    const int  M      = (int)(cacheN / ((long)D * DIM));  // 32768
    const int  DIM4   = DIM / 4;                          // 192

    float* out  = (float*)d_out;
    float* tail = ((long)out_size >= cacheN + 2L * D) ? (out + cacheN) : nullptr;

    const int nb_per_d = (M + 7) / 8;
    dim3 grid((unsigned)(nb_per_d + 1), (unsigned)D, 1);
    fused_kernel<<<grid, DIM4>>>((const float4*)cache,
                                 (const float4*)acts,
                                 mask, n_valid, index,
                                 (float4*)out, tail, D, T, M);
}

// round 10
// speedup vs baseline: 1.0188x; 1.0188x over previous
#include <cuda_runtime.h>
#include <cstdint>

// Compact per-row maps (no clearing needed):
//   g_tok[d*T + rank] = global token id of the rank-th kept token in row d
//   g_total/g_zero: kept count, special zeroed slot (-1 if none)
#define MAX_D  64
#define MAX_DT (8 * 32768)
__device__ int g_tok[MAX_DT];
__device__ int g_total[MAX_D];
__device__ int g_zero[MAX_D];
__device__ volatile int g_ready[MAX_D];   // 0 at process start; reset each launch
__device__ unsigned g_done;               // finished-block counter, reset each launch

__device__ __forceinline__ int mask_at(const void* mask, int mtype, long i) {
    if (mtype == 1) return ((const int*)mask)[i] != 0;          // int32
    if (mtype == 2) return ((const float*)mask)[i] != 0.0f;     // float32
    return ((const uint8_t*)mask)[i] != 0;                      // uint8/bool
}

// Setup for row d: mask scan -> g_tok/g_total/g_zero + tail outputs, then set
// g_ready[d]. Runs in D of ~32k blocks; __noinline__ keeps its register
// demand (spilled under the launch-bounds cap) off the copy blocks.
__device__ __noinline__ void setup_row(const void* __restrict__ mask,
                                       const int* __restrict__ n_valid,
                                       const int* __restrict__ index,
                                       float* __restrict__ out_tail,
                                       int D, int T, int M, int d)
{
    const int t  = threadIdx.x;
    const int NT = blockDim.x;

    // mask dtype probe over this row's first T bytes:
    // float32: 1.0f bytes 00 00 80 3f -> some byte > 1
    // int32  : nonzero bytes only at pos%4==0
    // uint8  : nonzero at pos%4!=0 (w.h.p.)
    __shared__ int s_gt1, s_nzmod;
    if (t == 0) { s_gt1 = 0; s_nzmod = 0; }
    __syncthreads();
    {
        const uint8_t* mb = (const uint8_t*)mask + (long)d * T;
        int gt1 = 0, nzmod = 0;
        for (int i = t; i < T; i += NT) {
            uint8_t b = mb[i];
            if (b > 1) gt1 = 1;
            else if (b != 0 && (i & 3)) nzmod = 1;
        }
        if (gt1)   atomicOr(&s_gt1, 1);
        if (nzmod) atomicOr(&s_nzmod, 1);
    }
    __syncthreads();

    const int mtype = s_gt1 ? 2 : (s_nzmod ? 0 : 1);
    const long mbase = (long)d * T;

    const int chunk = (T + NT - 1) / NT;
    const int start = t * chunk;

    int cnt = 0;
    for (int j = 0; j < chunk; ++j) {
        int tt = start + j;
        if (tt < T && mask_at(mask, mtype, mbase + tt)) cnt++;
    }

    // Block exclusive scan over per-thread counts.
    const unsigned lane = t & 31u;
    const unsigned wid  = t >> 5;
    int v = cnt;
    #pragma unroll
    for (int off = 1; off < 32; off <<= 1) {
        int n = __shfl_up_sync(0xffffffffu, v, off);
        if (lane >= (unsigned)off) v += n;
    }
    __shared__ int warp_tot[32];
    __shared__ int warp_pref[33];
    if (lane == 31) warp_tot[wid] = v;
    __syncthreads();
    if (t == 0) {
        int s = 0;
        int nw = (NT + 31) >> 5;
        for (int w = 0; w < nw; ++w) { warp_pref[w] = s; s += warp_tot[w]; }
        warp_pref[nw] = s;
    }
    __syncthreads();
    const int excl  = warp_pref[wid] + (v - cnt);
    const int total = warp_pref[(NT + 31) >> 5];

    int rank = excl;
    int* tok = g_tok + (long)d * T;
    for (int j = 0; j < chunk; ++j) {
        int tt = start + j;
        if (tt < T && mask_at(mask, mtype, mbase + tt)) {
            tok[rank++] = d * T + tt;      // global token id, in rank order
        }
    }

    if (t == 0) {
        const int idx0 = index[d];
        g_total[d] = total;
        // First token masked -> offsets[0] = -1 -> slot (index-1) mod M is
        // set(0)+add(0). Never collides with kept slots (total < M).
        int zs = -1;
        if (T > 0 && !mask_at(mask, mtype, mbase) && total < M) {
            zs = idx0 - 1;
            if (zs < 0) zs += M;
        }
        g_zero[d] = zs;
        if (out_tail) {
            long nv = (long)n_valid[d] + total;
            if (nv > M) nv = M;
            out_tail[d]     = (float)nv;                     // new_n_valid
            out_tail[D + d] = (float)((idx0 + total) % M);   // new_index
        }
    }

    __syncthreads();
    __threadfence();                 // publish g_* before the flag
    if (t == 0) g_ready[d] = 1;
}

// Slow write path: slots whose rank may select an acts source or the zeroed
// slot. ~12.6% of blocks; spins briefly on g_ready[d] (setup finishes within
// the first wave). __noinline__ keeps its registers off the fast path.
__device__ __noinline__ void write_slow(const float4* __restrict__ cache,
                                        const float4* __restrict__ acts,
                                        float4* __restrict__ out,
                                        int d, int idx0, int s0, int n,
                                        int T, int M, long rowd)
{
    const int t  = threadIdx.x;
    const int NT = blockDim.x;

    if (t == 0) { while (g_ready[d] == 0) __nanosleep(64); }
    __syncthreads();
    __threadfence();                // order g_* reads after flag

    const int total = g_total[d];
    const int zslot = g_zero[d];
    const int* tok  = g_tok + (long)d * T;

    for (int i = 0; i < n; ++i) {
        const int s = s0 + i;
        int rank = s - idx0; if (rank < 0) rank += M;
        const long r = rowd + s;
        const bool fa = rank < total;
        const int  tk = fa ? tok[rank] : 0;
        const float4* p = (fa ? acts + (long)tk * NT : cache + r * NT) + t;
        float4 v = __ldcs(p);
        if (s == zslot) v = make_float4(0.f, 0.f, 0.f, 0.f);
        __stcs(out + r * NT + t, v);
    }
}

// Single fused kernel. Grid (nb_per_d + 1, D), blockDim = DIM/4.
//  blockIdx.x == 0  : setup for row d.
//  blockIdx.x == x+1: covers slots 8x .. 8x+7 of row d (SLOT-DIRECT mapping:
//    identical DRAM access pattern to the 86.3%-of-peak split kernel).
//    A block needs setup results only if one of its ranks is < T (acts
//    source possible) or == M-1 (possible zeroed slot) -> ~12.6% of blocks.
__global__ void __launch_bounds__(192, 8)
fused_kernel(const float4* __restrict__ cache,
             const float4* __restrict__ acts,
             const void*  __restrict__ mask,
             const int*   __restrict__ n_valid,
             const int*   __restrict__ index,
             float4* __restrict__ out,
             float*  __restrict__ out_tail,
             int D, int T, int M)
{
    const int t  = threadIdx.x;
    const int NT = blockDim.x;       // = DIM/4 = 192
    const int d  = blockIdx.y;

    if (blockIdx.x == 0) {
        setup_row(mask, n_valid, index, out_tail, D, T, M, d);
    } else {
        const int s0   = (blockIdx.x - 1) * 8;
        const int idx0 = index[d];              // raw input: no setup dependency
        const long rowd = (long)d * M;

        int rank0 = s0 - idx0;
        if (rank0 < 0) rank0 += M;
        // Block covers ranks rank0..rank0+7 (mod M).
        const bool needs_sync = (rank0 < T) || (rank0 >= M - 8);

        if (s0 + 7 < M && !needs_sync) {
            // ranks in [T, M-2]: pure cache -> out copy at this block's slots.
            const long base = (rowd + s0) * NT + t;
            float4 v[8];
            #pragma unroll
            for (int i = 0; i < 8; ++i) v[i] = __ldcs(cache + base + (long)i * NT);
            #pragma unroll
            for (int i = 0; i < 8; ++i) __stcs(out + base + (long)i * NT, v[i]);
        } else {
            const int n = (s0 + 8 <= M) ? 8 : (M - s0);
            write_slow(cache, acts, out, d, idx0, s0, n, T, M, rowd);
        }
    }

    // -------- launch-epilogue: last finished block resets the flags --------
    if (t == 0) {
        const unsigned nb = gridDim.x * gridDim.y;
        const unsigned v = atomicAdd(&g_done, 1u);
        if (v == nb - 1u) {
            for (int i = 0; i < D && i < MAX_D; ++i) g_ready[i] = 0;
            __threadfence();
            g_done = 0;
        }
    }
}

extern "C" void kernel_launch(void* const* d_in, const int* in_sizes, int n_in,
                              void* d_out, int out_size)
{
    const float* cache   = (const float*)d_in[0];
    const float* acts    = (const float*)d_in[1];
    const void*  mask    = (const void*)d_in[2];
    const int*   n_valid = (const int*)d_in[3];
    const int*   index   = (const int*)d_in[4];

    const int  D      = in_sizes[3];                      // 8
    const long DT     = (long)in_sizes[2];                // D*T
    const int  T      = (int)(DT / D);                    // 4096
    const int  DIM    = (int)((long)in_sizes[1] / DT);    // 768
    const long cacheN = (long)in_sizes[0];                // D*M*DIM
    const int  M      = (int)(cacheN / ((long)D * DIM));  // 32768
    const int  DIM4   = DIM / 4;                          // 192

    float* out  = (float*)d_out;
    float* tail = ((long)out_size >= cacheN + 2L * D) ? (out + cacheN) : nullptr;

    const int nb_per_d = (M + 7) / 8;
    dim3 grid((unsigned)(nb_per_d + 1), (unsigned)D, 1);
    fused_kernel<<<grid, DIM4>>>((const float4*)cache,
                                 (const float4*)acts,
                                 mask, n_valid, index,
                                 (float4*)out, tail, D, T, M);
}